// round 12
// baseline (speedup 1.0000x reference)
#include <cuda_runtime.h>
#include <cuda_bf16.h>
#include <cstdint>

#define BATCH 4
#define NPTS  4096
#define DIM   64
#define LOG2E 1.4426950408889634f
#define SC_F  24.0224478f          // sqrt(log2e)/0.05
#define TWOL  2.8853900817779268f  // 2*log2e

#define BM 64
#define BN 64
#define NJT (NPTS/BN)   // 64
#define NIT (NPTS/BM)   // 64

#define ROWB 272                    // 256B packed row + 16B pad (bf16 tiles)
#define STRF 68                     // score row stride in floats (272B)

#define OFF_A 0
#define SZ_A  (64*ROWB)             // 17408
#define OFF_B SZ_A                  // 17408 ; 2 x 17408
#define SZ_B  (64*ROWB)
#define OFF_S (OFF_B + 2*SZ_B)      // 52224 ; 2 x 17408 score bufs
#define SZ_S  (64*STRF*4)           // 17408
#define OFF_P (OFF_S + 2*SZ_S)      // 87040 ; 4 x 1280 (xj float4 / cn2)
#define SZ_P  1280
#define OFF_R (OFF_P + 4*SZ_P)      // 92160
#define SMEM_TOTAL (OFF_R + 64)     // 92224

// scratch (no allocation allowed)
__device__ __align__(16) uint32_t g_pk1[BATCH*NPTS*64]; // [hi64|lo64] bf16, f1*2log2e
__device__ __align__(16) uint32_t g_pk2[BATCH*NPTS*64]; // [hi64|lo64] bf16, f2 raw
__device__ __align__(16) float4   g_pi[BATCH*NPTS];     // xi*SC
__device__ __align__(16) float4   g_pj[BATCH*NPTS];     // xj*SC, w = -|xj|^2
__device__ __align__(16) float    g_cn2[BATCH*NPTS];    // log2e*|f2|^2
__device__ float g_partial[BATCH*NIT];

__device__ __forceinline__ float ex2(float x){
    float y; asm("ex2.approx.ftz.f32 %0, %1;" : "=f"(y) : "f"(x)); return y;
}
__device__ __forceinline__ void cpa16(uint32_t dst, const void* src){
    asm volatile("cp.async.cg.shared.global [%0], [%1], 16;\n" :: "r"(dst), "l"(src));
}
__device__ __forceinline__ void ldmx4(uint32_t& r0,uint32_t& r1,uint32_t& r2,uint32_t& r3, uint32_t a){
    asm volatile("ldmatrix.sync.aligned.m8n8.x4.shared.b16 {%0,%1,%2,%3}, [%4];\n"
                 : "=r"(r0),"=r"(r1),"=r"(r2),"=r"(r3) : "r"(a));
}
__device__ __forceinline__ void mma16816(float* c, const uint32_t* a, uint32_t b0, uint32_t b1){
    asm volatile("mma.sync.aligned.m16n8k16.row.col.f32.bf16.bf16.f32 "
                 "{%0,%1,%2,%3}, {%4,%5,%6,%7}, {%8,%9}, {%0,%1,%2,%3};\n"
                 : "+f"(c[0]),"+f"(c[1]),"+f"(c[2]),"+f"(c[3])
                 : "r"(a[0]),"r"(a[1]),"r"(a[2]),"r"(a[3]), "r"(b0),"r"(b1));
}
#define BAR_SYNC(id,n)   asm volatile("bar.sync %0, %1;"   :: "r"(id), "r"(n) : "memory")
#define BAR_ARRIVE(id,n) asm volatile("bar.arrive %0, %1;" :: "r"(id), "r"(n) : "memory")

// ---------------------------------------------------------------------------
__global__ void prep_kernel(const float* __restrict__ pts,
                            const float* __restrict__ f1,
                            const float* __restrict__ f2)
{
    int gw   = (blockIdx.x*blockDim.x + threadIdx.x) >> 5;
    int lane = threadIdx.x & 31;
    if (gw >= BATCH*NPTS) return;
    const float* r1 = f1 + (size_t)gw*DIM;
    const float* r2 = f2 + (size_t)gw*DIM;
    float a0 = r1[lane], a1 = r1[lane+32];
    float b0 = r2[lane], b1 = r2[lane+32];
    float n2 = b0*b0 + b1*b1;
    #pragma unroll
    for (int o=16;o>=1;o>>=1) n2 += __shfl_xor_sync(~0u,n2,o);

    float s0 = a0*TWOL, s1 = a1*TWOL;
    __nv_bfloat16 h0=__float2bfloat16(s0), h1=__float2bfloat16(s1);
    __nv_bfloat16 l0=__float2bfloat16(s0-__bfloat162float(h0));
    __nv_bfloat16 l1=__float2bfloat16(s1-__bfloat162float(h1));
    __nv_bfloat16* o1 = (__nv_bfloat16*)(g_pk1 + (size_t)gw*64);
    o1[lane]=h0; o1[32+lane]=h1; o1[64+lane]=l0; o1[96+lane]=l1;

    __nv_bfloat16 H0=__float2bfloat16(b0), H1=__float2bfloat16(b1);
    __nv_bfloat16 L0=__float2bfloat16(b0-__bfloat162float(H0));
    __nv_bfloat16 L1=__float2bfloat16(b1-__bfloat162float(H1));
    __nv_bfloat16* o2 = (__nv_bfloat16*)(g_pk2 + (size_t)gw*64);
    o2[lane]=H0; o2[32+lane]=H1; o2[64+lane]=L0; o2[96+lane]=L1;

    if (lane==0){
        float px = pts[(size_t)gw*3+0]*SC_F;
        float py = pts[(size_t)gw*3+1]*SC_F;
        float pz = pts[(size_t)gw*3+2]*SC_F;
        g_pi[gw]  = make_float4(px,py,pz,0.0f);
        g_pj[gw]  = make_float4(px,py,pz, -fmaf(px,px, fmaf(py,py, pz*pz)));
        g_cn2[gw] = n2*LOG2E;
    }
}

// ---------------------------------------------------------------------------
// Warp-specialized loss kernel. 256 thr: warps 0-3 = MMA producers (16 rows
// x 64 cols each, A frags in regs), warps 4-7 = epilogue consumers reading
// scores in fragment layout (lane-matched to producer lane). Named barriers:
// FULL[b]=1+b, FREE[b]=3+b (count 256); producer bar 5, consumer bar 6 (128).
// Fixed-scale accumulation (no online max).
// ---------------------------------------------------------------------------
__global__ __launch_bounds__(256,2)
void loss_kernel(const float* __restrict__ wts)
{
    extern __shared__ __align__(16) char smem[];
    const uint32_t sb = (uint32_t)__cvta_generic_to_shared(smem);
    const int b  = blockIdx.y;
    const int i0 = blockIdx.x*BM;
    const int tid = threadIdx.x;
    const int lane = tid & 31;
    float* sR = (float*)(smem + OFF_R);

    if (tid < 128){
        // ===================== PRODUCERS =====================
        const int pw = tid >> 5;
        {
            const char* gA  = (const char*)(g_pk1 + (size_t)(b*NPTS+i0)*64);
            const char* gB0 = (const char*)(g_pk2 + (size_t)(b*NPTS)*64);
            const char* gB1 = (const char*)(g_pk2 + (size_t)(b*NPTS + BN)*64);
            #pragma unroll
            for(int q=0;q<8;q++){
                int idx=q*128+tid, r=idx>>4, c=idx&15;
                cpa16(sb + OFF_A + r*ROWB + c*16, gA + r*256 + c*16);
                cpa16(sb + OFF_B + r*ROWB + c*16, gB0 + r*256 + c*16);
            }
            asm volatile("cp.async.commit_group;\n");
            #pragma unroll
            for(int q=0;q<8;q++){
                int idx=q*128+tid, r=idx>>4, c=idx&15;
                cpa16(sb + OFF_B + SZ_B + r*ROWB + c*16, gB1 + r*256 + c*16);
            }
            asm volatile("cp.async.commit_group;\n");
        }
        const uint32_t aAddr = sb + OFF_A + (pw*16 + (lane&15))*ROWB + (lane>>4)*16;
        const int bn_row = (lane&7) + (((lane>>4)&1)<<3);
        const uint32_t bk16 = ((lane>>3)&1)*16;
        const int g = lane>>2, tig = lane&3;

        asm volatile("cp.async.wait_group 1;\n" ::: "memory");
        BAR_SYNC(5,128);
        uint32_t ah[4][4], al[4][4];
        #pragma unroll
        for(int c=0;c<4;c++){
            ldmx4(ah[c][0],ah[c][1],ah[c][2],ah[c][3], aAddr + c*32);
            ldmx4(al[c][0],al[c][1],al[c][2],al[c][3], aAddr + 128 + c*32);
        }

        for(int t=0; t<NJT; t++){
            const int buf = t&1;
            if (t >= 1){
                asm volatile("cp.async.wait_group 1;\n" ::: "memory");
                BAR_SYNC(5,128);
            }
            float acc[8][4];
            #pragma unroll
            for(int nb=0;nb<8;nb++)
                #pragma unroll
                for(int q=0;q<4;q++) acc[nb][q]=0.f;
            const uint32_t pB = sb + OFF_B + buf*SZ_B;
            #pragma unroll
            for(int c=0;c<4;c++){
                uint32_t bh[4][4], bl[4][4];
                #pragma unroll
                for(int n16=0;n16<4;n16++){
                    uint32_t ba = pB + (n16*16 + bn_row)*ROWB + bk16;
                    ldmx4(bh[n16][0],bh[n16][1],bh[n16][2],bh[n16][3], ba + c*32);
                    ldmx4(bl[n16][0],bl[n16][1],bl[n16][2],bl[n16][3], ba + 128 + c*32);
                }
                #pragma unroll
                for(int n16=0;n16<4;n16++){
                    mma16816(acc[n16*2+0], ah[c], bh[n16][0], bh[n16][1]);
                    mma16816(acc[n16*2+1], ah[c], bh[n16][2], bh[n16][3]);
                    mma16816(acc[n16*2+0], ah[c], bl[n16][0], bl[n16][1]);
                    mma16816(acc[n16*2+1], ah[c], bl[n16][2], bl[n16][3]);
                    mma16816(acc[n16*2+0], al[c], bh[n16][0], bh[n16][1]);
                    mma16816(acc[n16*2+1], al[c], bh[n16][2], bh[n16][3]);
                }
            }
            BAR_SYNC(5,128);        // all producers done reading B buf
            if (t+2 < NJT){
                const char* gB = (const char*)(g_pk2 + (size_t)(b*NPTS + (t+2)*BN)*64);
                const uint32_t dst = sb + OFF_B + buf*SZ_B;
                #pragma unroll
                for(int q=0;q<8;q++){
                    int idx=q*128+tid, r=idx>>4, c=idx&15;
                    cpa16(dst + r*ROWB + c*16, gB + r*256 + c*16);
                }
                asm volatile("cp.async.commit_group;\n");
            }
            if (t >= 2) BAR_SYNC(3+buf, 256);      // wait score buf freed
            // store scores in fragment layout
            {
                float* Sp = (float*)(smem + OFF_S + buf*SZ_S);
                #pragma unroll
                for(int nb=0;nb<8;nb++){
                    int base = (pw*16+g)*STRF + nb*8 + tig*2;
                    *(float2*)(Sp + base)          = make_float2(acc[nb][0], acc[nb][1]);
                    *(float2*)(Sp + base + 8*STRF) = make_float2(acc[nb][2], acc[nb][3]);
                }
            }
            __threadfence_block();
            BAR_ARRIVE(1+buf, 256);                // score buf full
        }
    } else {
        // ===================== CONSUMERS =====================
        const int tid2 = tid - 128;
        const int cw = tid2 >> 5;
        const int g = lane>>2, tig = lane&3;
        #define LOAD_P(t_) do{ \
            int jj = (t_)*BN; \
            uint32_t pd = sb + OFF_P + ((t_)&3)*SZ_P; \
            if (tid2 < 64) cpa16(pd + tid2*16, (const char*)(g_pj + b*NPTS + jj + tid2)); \
            else if (tid2 < 80) cpa16(pd + 1024 + (tid2-64)*16, \
                                      (const char*)(g_cn2 + b*NPTS + jj + (tid2-64)*4)); \
            asm volatile("cp.async.commit_group;\n"); \
        }while(0)
        LOAD_P(0); LOAD_P(1); LOAD_P(2);

        const int ra = cw*16 + g;                  // my rows: ra, ra+8
        float4 vi0 = g_pi[b*NPTS + i0 + ra];
        float4 vi1 = g_pi[b*NPTS + i0 + ra + 8];
        const float x2x0=vi0.x+vi0.x, x2y0=vi0.y+vi0.y, x2z0=vi0.z+vi0.z;
        const float nni0=-fmaf(vi0.x,vi0.x, fmaf(vi0.y,vi0.y, vi0.z*vi0.z));
        const float x2x1=vi1.x+vi1.x, x2y1=vi1.y+vi1.y, x2z1=vi1.z+vi1.z;
        const float nni1=-fmaf(vi1.x,vi1.x, fmaf(vi1.y,vi1.y, vi1.z*vi1.z));

        float Z1a=0.f,Z2a=0.f,Aa=0.f,Ba=0.f,Ca=0.f;
        float Z1b=0.f,Z2b=0.f,Ab=0.f,Bb=0.f,Cb=0.f;

        for(int t=0; t<NJT; t++){
            const int buf = t&1;
            asm volatile("cp.async.wait_group 2;\n" ::: "memory");
            BAR_SYNC(6,128);                        // P(t) visible
            if (t+3 < NJT) LOAD_P(t+3);
            BAR_SYNC(1+buf, 256);                   // scores ready
            const float*  S   = (const float*)(smem + OFF_S + buf*SZ_S);
            const float4* pjS = (const float4*)(smem + OFF_P + (t&3)*SZ_P);
            const float*  cnS = (const float*) (smem + OFF_P + (t&3)*SZ_P + 1024);
            #pragma unroll
            for(int nb=0;nb<8;nb++){
                int col = nb*8 + tig*2;
                float2 s0 = *(const float2*)(S + ra*STRF + col);
                float2 s1 = *(const float2*)(S + (ra+8)*STRF + col);
                float2 cn = *(const float2*)(cnS + col);
                #pragma unroll
                for(int q=0;q<2;q++){
                    float4 v = pjS[col+q];
                    float sc0 = q ? s0.y : s0.x;
                    float sc1 = q ? s1.y : s1.x;
                    float cnq = q ? cn.y : cn.x;
                    float e2a = ex2(sc0 - cnq);
                    float e2b = ex2(sc1 - cnq);
                    float t0 = fmaf(x2x0, v.x, fmaf(x2y0, v.y, fmaf(x2z0, v.z, v.w))) + nni0;
                    float t1 = fmaf(x2x1, v.x, fmaf(x2y1, v.y, fmaf(x2z1, v.z, v.w))) + nni1;
                    float e1a = ex2(t0);
                    float e1b = ex2(t1);
                    Z1a += e1a; Aa = fmaf(e1a,e1a,Aa);
                    Z2a += e2a; Ba = fmaf(e2a,e2a,Ba);
                    Ca = fmaf(e1a,e2a,Ca);
                    Z1b += e1b; Ab = fmaf(e1b,e1b,Ab);
                    Z2b += e2b; Bb = fmaf(e2b,e2b,Bb);
                    Cb = fmaf(e1b,e2b,Cb);
                }
            }
            BAR_ARRIVE(3+buf, 256);                 // score buf freed
        }
        // merge the 4 tig lanes per row (plain sums)
        #pragma unroll
        for(int off=1; off<=2; off<<=1){
            Z1a += __shfl_xor_sync(~0u, Z1a, off);
            Z2a += __shfl_xor_sync(~0u, Z2a, off);
            Aa  += __shfl_xor_sync(~0u, Aa,  off);
            Ba  += __shfl_xor_sync(~0u, Ba,  off);
            Ca  += __shfl_xor_sync(~0u, Ca,  off);
            Z1b += __shfl_xor_sync(~0u, Z1b, off);
            Z2b += __shfl_xor_sync(~0u, Z2b, off);
            Ab  += __shfl_xor_sync(~0u, Ab,  off);
            Bb  += __shfl_xor_sync(~0u, Bb,  off);
            Cb  += __shfl_xor_sync(~0u, Cb,  off);
        }
        float wacc = 0.0f;
        if (tig == 0){
            float i1 = 1.0f/Z1a, i2 = 1.0f/Z2a;
            float lossA = Aa*i1*i1 - 2.0f*((Ca*i2)*i1) + (Ba*i2)*i2;
            float j1 = 1.0f/Z1b, j2 = 1.0f/Z2b;
            float lossB = Ab*j1*j1 - 2.0f*((Cb*j2)*j1) + (Bb*j2)*j2;
            wacc = wts[b*NPTS + i0 + ra]*lossA + wts[b*NPTS + i0 + ra + 8]*lossB;
        }
        #pragma unroll
        for(int off=16; off>=1; off>>=1) wacc += __shfl_xor_sync(~0u, wacc, off);
        if (lane==0) sR[cw] = wacc;
        #undef LOAD_P
    }

    __syncthreads();
    if (tid==0)
        g_partial[b*NIT + blockIdx.x] = (sR[0]+sR[1]) + (sR[2]+sR[3]);
}

// ---------------------------------------------------------------------------
__global__ void reduce_kernel(float* __restrict__ out)
{
    int b    = threadIdx.x >> 5;
    int lane = threadIdx.x & 31;
    float s = g_partial[b*NIT + lane] + g_partial[b*NIT + 32 + lane];
    #pragma unroll
    for(int off=16; off>=1; off>>=1) s += __shfl_xor_sync(~0u, s, off);
    if (lane==0) out[b] = s;
}

// ---------------------------------------------------------------------------
extern "C" void kernel_launch(void* const* d_in, const int* in_sizes, int n_in,
                              void* d_out, int out_size)
{
    const float* pts = (const float*)d_in[0];
    const float* wts = (const float*)d_in[1];
    const float* f1  = (const float*)d_in[2];
    const float* f2  = (const float*)d_in[3];
    float* out = (float*)d_out;

    cudaFuncSetAttribute(loss_kernel, cudaFuncAttributeMaxDynamicSharedMemorySize, SMEM_TOTAL);
    prep_kernel<<<(BATCH*NPTS)/8, 256>>>(pts, f1, f2);
    dim3 grid(NIT, BATCH);
    loss_kernel<<<grid, 256, SMEM_TOTAL>>>(wts);
    reduce_kernel<<<1, 128>>>(out);
}

// round 13
// speedup vs baseline: 1.3532x; 1.3532x over previous
#include <cuda_runtime.h>
#include <cuda_bf16.h>
#include <cstdint>

#define BATCH 4
#define NPTS  4096
#define DIM   64
#define LOG2E 1.4426950408889634f
#define SC_F  24.0224478f          // sqrt(log2e)/0.05
#define TWOL  2.8853900817779268f  // 2*log2e

#define BM 64
#define BN 64
#define NJT (NPTS/BN)   // 64
#define NIT (NPTS/BM)   // 64

#define ROWB 272                    // 256B packed row + 16B pad
#define OFF_A 0
#define SZ_A  (64*ROWB)             // 17408
#define OFF_B (SZ_A)                // 17408
#define SZ_B  (64*ROWB)             // 17408
#define OFF_P (OFF_B + 2*SZ_B)      // 52224
#define SZ_P  1280                  // [0,1024) float4 xj ; [1024,1280) cn2
#define OFF_M (OFF_P + 4*SZ_P)      // 57344 ; 64 rows x 5 floats
#define OFF_R (OFF_M + 64*5*4)      // 58624
#define SMEM_TOTAL (OFF_R + 64)     // 58688

// scratch (no allocation allowed)
__device__ __align__(16) uint32_t g_pk1[BATCH*NPTS*64]; // [hi64|lo64] bf16, f1*2log2e
__device__ __align__(16) uint32_t g_pk2[BATCH*NPTS*64]; // [hi64|lo64] bf16, f2 raw
__device__ __align__(16) float4   g_pi[BATCH*NPTS];     // xi*SC
__device__ __align__(16) float4   g_pj[BATCH*NPTS];     // xj*SC, w = -|xj|^2
__device__ __align__(16) float    g_cn2[BATCH*NPTS];    // log2e*|f2|^2
__device__ float g_partial[BATCH*NIT];

__device__ __forceinline__ float ex2(float x){
    float y; asm("ex2.approx.ftz.f32 %0, %1;" : "=f"(y) : "f"(x)); return y;
}
__device__ __forceinline__ void cpa16(uint32_t dst, const void* src){
    asm volatile("cp.async.cg.shared.global [%0], [%1], 16;\n" :: "r"(dst), "l"(src));
}
__device__ __forceinline__ void ldmx4(uint32_t& r0,uint32_t& r1,uint32_t& r2,uint32_t& r3, uint32_t a){
    asm volatile("ldmatrix.sync.aligned.m8n8.x4.shared.b16 {%0,%1,%2,%3}, [%4];\n"
                 : "=r"(r0),"=r"(r1),"=r"(r2),"=r"(r3) : "r"(a));
}
__device__ __forceinline__ void mma16816(float* c, const uint32_t* a, uint32_t b0, uint32_t b1){
    asm volatile("mma.sync.aligned.m16n8k16.row.col.f32.bf16.bf16.f32 "
                 "{%0,%1,%2,%3}, {%4,%5,%6,%7}, {%8,%9}, {%0,%1,%2,%3};\n"
                 : "+f"(c[0]),"+f"(c[1]),"+f"(c[2]),"+f"(c[3])
                 : "r"(a[0]),"r"(a[1]),"r"(a[2]),"r"(a[3]), "r"(b0),"r"(b1));
}

// ---------------------------------------------------------------------------
__global__ void prep_kernel(const float* __restrict__ pts,
                            const float* __restrict__ f1,
                            const float* __restrict__ f2)
{
    int gw   = (blockIdx.x*blockDim.x + threadIdx.x) >> 5;
    int lane = threadIdx.x & 31;
    if (gw >= BATCH*NPTS) return;
    const float* r1 = f1 + (size_t)gw*DIM;
    const float* r2 = f2 + (size_t)gw*DIM;
    float a0 = r1[lane], a1 = r1[lane+32];
    float b0 = r2[lane], b1 = r2[lane+32];
    float n2 = b0*b0 + b1*b1;
    #pragma unroll
    for (int o=16;o>=1;o>>=1) n2 += __shfl_xor_sync(~0u,n2,o);

    float s0 = a0*TWOL, s1 = a1*TWOL;
    __nv_bfloat16 h0=__float2bfloat16(s0), h1=__float2bfloat16(s1);
    __nv_bfloat16 l0=__float2bfloat16(s0-__bfloat162float(h0));
    __nv_bfloat16 l1=__float2bfloat16(s1-__bfloat162float(h1));
    __nv_bfloat16* o1 = (__nv_bfloat16*)(g_pk1 + (size_t)gw*64);
    o1[lane]=h0; o1[32+lane]=h1; o1[64+lane]=l0; o1[96+lane]=l1;

    __nv_bfloat16 H0=__float2bfloat16(b0), H1=__float2bfloat16(b1);
    __nv_bfloat16 L0=__float2bfloat16(b0-__bfloat162float(H0));
    __nv_bfloat16 L1=__float2bfloat16(b1-__bfloat162float(H1));
    __nv_bfloat16* o2 = (__nv_bfloat16*)(g_pk2 + (size_t)gw*64);
    o2[lane]=H0; o2[32+lane]=H1; o2[64+lane]=L0; o2[96+lane]=L1;

    if (lane==0){
        float px = pts[(size_t)gw*3+0]*SC_F;
        float py = pts[(size_t)gw*3+1]*SC_F;
        float pz = pts[(size_t)gw*3+2]*SC_F;
        g_pi[gw]  = make_float4(px,py,pz,0.0f);
        g_pj[gw]  = make_float4(px,py,pz, -fmaf(px,px, fmaf(py,py, pz*pz)));
        g_cn2[gw] = n2*LOG2E;
    }
}

// ---------------------------------------------------------------------------
__device__ __forceinline__ void load_B_tile(uint32_t sb, int tid, int b, int jt){
    const char* gB = (const char*)(g_pk2 + (size_t)(b*NPTS + jt*BN)*64);
    const uint32_t dst = sb + OFF_B + (jt&1)*SZ_B;
    #pragma unroll
    for(int q=0;q<4;q++){
        int idx=q*256+tid, r=idx>>4, c=idx&15;
        cpa16(dst + r*ROWB + c*16, gB + r*256 + c*16);
    }
    const uint32_t pdst = sb + OFF_P + (jt&3)*SZ_P;
    const int j0 = jt*BN;
    if (tid<64) cpa16(pdst + tid*16, (const char*)(g_pj + b*NPTS + j0 + tid));
    else if (tid<80) cpa16(pdst + 1024 + (tid-64)*16,
                           (const char*)(g_cn2 + b*NPTS + j0 + (tid-64)*4));
}

// ---------------------------------------------------------------------------
// 256 thr = 8 warps: wm=w&3 (row band of 16), wn=w>>2 (col band of 32).
// Warp tile 16 rows x 32 cols; A fragments in registers across all tiles.
// Fixed-scale accumulation (no online max; validated in R12, rel_err 1e-6).
// ---------------------------------------------------------------------------
__global__ __launch_bounds__(256,2)
void loss_kernel(const float* __restrict__ wts)
{
    extern __shared__ __align__(16) char smem[];
    const uint32_t sb = (uint32_t)__cvta_generic_to_shared(smem);
    const int b  = blockIdx.y;
    const int i0 = blockIdx.x*BM;
    const int tid = threadIdx.x;
    const int w = tid>>5, lane = tid&31;
    const int wm = w&3, wn = w>>2;
    const int g = lane>>2, tig = lane&3;

    // prologue: A + B0 + P0 (group0), B1 + P1 (group1)
    {
        const char* gA = (const char*)(g_pk1 + (size_t)(b*NPTS+i0)*64);
        #pragma unroll
        for(int q=0;q<4;q++){
            int idx=q*256+tid, r=idx>>4, c=idx&15;
            cpa16(sb + OFF_A + r*ROWB + c*16, gA + r*256 + c*16);
        }
        load_B_tile(sb, tid, b, 0);
        asm volatile("cp.async.commit_group;\n");
        load_B_tile(sb, tid, b, 1);
        asm volatile("cp.async.commit_group;\n");
    }

    const uint32_t aAddr = sb + OFF_A + (wm*16 + (lane&15))*ROWB + (lane>>4)*16;
    const int bn_row = (lane&7) + (((lane>>4)&1)<<3);
    const uint32_t bk16 = ((lane>>3)&1)*16;

    // per-thread rows: r0 = wm*16+g, r1 = r0+8
    float x2x[2],x2y[2],x2z[2],nni[2];
    #pragma unroll
    for(int h=0;h<2;h++){
        int rl = wm*16 + g + h*8;
        float4 v = g_pi[b*NPTS + i0 + rl];
        x2x[h]=v.x+v.x; x2y[h]=v.y+v.y; x2z[h]=v.z+v.z;
        nni[h]=-fmaf(v.x,v.x, fmaf(v.y,v.y, v.z*v.z));
    }
    float Z1[2],Z2[2],Av[2],Bv[2],Cv[2];
    #pragma unroll
    for(int h=0;h<2;h++){ Z1[h]=0.f;Z2[h]=0.f;Av[h]=0.f;Bv[h]=0.f;Cv[h]=0.f; }

    asm volatile("cp.async.wait_group 1;\n" ::: "memory");
    __syncthreads();

    // hoist A fragments (hi and lo): 8 ldmatrix.x4 = 32 regs
    uint32_t ah[4][4], al[4][4];
    #pragma unroll
    for(int c=0;c<4;c++){
        ldmx4(ah[c][0],ah[c][1],ah[c][2],ah[c][3], aAddr + c*32);
        ldmx4(al[c][0],al[c][1],al[c][2],al[c][3], aAddr + 128 + c*32);
    }

    for(int jt=0; jt<NJT; jt++){
        const int buf = jt&1;
        // ---- MMA: 4 k16-chunks x {HH,HL,LH}; B-only ldmatrix ----
        float acc[4][4];
        #pragma unroll
        for(int nb=0;nb<4;nb++)
            #pragma unroll
            for(int q=0;q<4;q++) acc[nb][q]=0.f;
        #pragma unroll
        for(int c=0;c<4;c++){
            #pragma unroll
            for(int n2=0;n2<2;n2++){
                uint32_t ba = sb + OFF_B + buf*SZ_B
                            + (wn*32 + n2*16 + bn_row)*ROWB + bk16;
                uint32_t bh[4], bl[4];
                ldmx4(bh[0],bh[1],bh[2],bh[3], ba + c*32);
                ldmx4(bl[0],bl[1],bl[2],bl[3], ba + 128 + c*32);
                mma16816(acc[n2*2+0], ah[c], bh[0], bh[1]);
                mma16816(acc[n2*2+1], ah[c], bh[2], bh[3]);
                mma16816(acc[n2*2+0], ah[c], bl[0], bl[1]);
                mma16816(acc[n2*2+1], ah[c], bl[2], bl[3]);
                mma16816(acc[n2*2+0], al[c], bh[0], bh[1]);
                mma16816(acc[n2*2+1], al[c], bh[2], bh[3]);
            }
        }

        // sync off the B buffer we just read, then prefetch jt+2 into it
        if (jt+1 < NJT){
            asm volatile("cp.async.wait_group 0;\n" ::: "memory");
        }
        __syncthreads();
        if (jt+2 < NJT){
            load_B_tile(sb, tid, b, jt+2);
            asm volatile("cp.async.commit_group;\n");
        }

        // ---- epilogue (fixed scale, no max) ----
        {
            const float4* pP = (const float4*)(smem + OFF_P + (jt&3)*SZ_P);
            const float*  pC = (const float*) (smem + OFF_P + (jt&3)*SZ_P + 1024);
            #pragma unroll
            for(int nb=0;nb<4;nb++){
                #pragma unroll
                for(int q=0;q<2;q++){
                    int c = wn*32 + nb*8 + tig*2 + q;
                    float4 v = pP[c];
                    float cn = pC[c];
                    #pragma unroll
                    for(int h=0;h<2;h++){
                        float e2 = ex2(acc[nb][h*2+q] - cn);
                        float tt = fmaf(x2x[h], v.x, fmaf(x2y[h], v.y,
                                   fmaf(x2z[h], v.z, v.w))) + nni[h];
                        float e1 = ex2(tt);
                        Z1[h]+=e1; Av[h]=fmaf(e1,e1,Av[h]);
                        Z2[h]+=e2; Bv[h]=fmaf(e2,e2,Bv[h]);
                        Cv[h]=fmaf(e1,e2,Cv[h]);
                    }
                }
            }
        }
    }

    // ---- merge 4 tig-lanes per row (plain sums) ----
    #pragma unroll
    for(int h=0;h<2;h++){
        #pragma unroll
        for(int off=1; off<=2; off<<=1){
            Z1[h] += __shfl_xor_sync(~0u, Z1[h], off);
            Z2[h] += __shfl_xor_sync(~0u, Z2[h], off);
            Av[h] += __shfl_xor_sync(~0u, Av[h], off);
            Bv[h] += __shfl_xor_sync(~0u, Bv[h], off);
            Cv[h] += __shfl_xor_sync(~0u, Cv[h], off);
        }
    }
    // ---- merge the two wn col-bands via smem ----
    float* sM = (float*)(smem + OFF_M);
    float* sR = (float*)(smem + OFF_R);
    if (wn==1 && tig==0){
        #pragma unroll
        for(int h=0;h<2;h++){
            int rl = wm*16 + g + h*8;
            float* p = sM + rl*5;
            p[0]=Z1[h]; p[1]=Z2[h]; p[2]=Av[h]; p[3]=Bv[h]; p[4]=Cv[h];
        }
    }
    __syncthreads();
    float wacc = 0.0f;
    if (wn==0 && tig==0){
        #pragma unroll
        for(int h=0;h<2;h++){
            int rl = wm*16 + g + h*8;
            const float* p = sM + rl*5;
            float Z1m = Z1[h] + p[0];
            float Z2m = Z2[h] + p[1];
            float Am  = Av[h] + p[2];
            float Bm  = Bv[h] + p[3];
            float Cm  = Cv[h] + p[4];
            float i1 = 1.0f/Z1m, i2 = 1.0f/Z2m;
            float loss = Am*i1*i1 - 2.0f*((Cm*i2)*i1) + (Bm*i2)*i2;
            wacc += wts[b*NPTS + i0 + rl] * loss;
        }
    }
    #pragma unroll
    for(int off=16; off>=1; off>>=1) wacc += __shfl_xor_sync(~0u, wacc, off);
    if (wn==0 && lane==0) sR[wm] = wacc;
    __syncthreads();
    if (tid==0)
        g_partial[b*NIT + blockIdx.x] = (sR[0]+sR[1]) + (sR[2]+sR[3]);
}

// ---------------------------------------------------------------------------
__global__ void reduce_kernel(float* __restrict__ out)
{
    int b    = threadIdx.x >> 5;
    int lane = threadIdx.x & 31;
    float s = g_partial[b*NIT + lane] + g_partial[b*NIT + 32 + lane];
    #pragma unroll
    for(int off=16; off>=1; off>>=1) s += __shfl_xor_sync(~0u, s, off);
    if (lane==0) out[b] = s;
}

// ---------------------------------------------------------------------------
extern "C" void kernel_launch(void* const* d_in, const int* in_sizes, int n_in,
                              void* d_out, int out_size)
{
    const float* pts = (const float*)d_in[0];
    const float* wts = (const float*)d_in[1];
    const float* f1  = (const float*)d_in[2];
    const float* f2  = (const float*)d_in[3];
    float* out = (float*)d_out;

    cudaFuncSetAttribute(loss_kernel, cudaFuncAttributeMaxDynamicSharedMemorySize, SMEM_TOTAL);
    prep_kernel<<<(BATCH*NPTS)/8, 256>>>(pts, f1, f2);
    dim3 grid(NIT, BATCH);
    loss_kernel<<<grid, 256, SMEM_TOTAL>>>(wts);
    reduce_kernel<<<1, 128>>>(out);
}

// round 14
// speedup vs baseline: 1.3828x; 1.0219x over previous
#include <cuda_runtime.h>
#include <cuda_bf16.h>
#include <cstdint>

#define BATCH 4
#define NPTS  4096
#define DIM   64
#define LOG2E 1.4426950408889634f
#define SC_F  24.0224478f          // sqrt(log2e)/0.05
#define TWOL  2.8853900817779268f  // 2*log2e

#define BM 64
#define BN 64
#define NJT (NPTS/BN)   // 64
#define NIT (NPTS/BM)   // 64

#define ROWB 272                    // 256B packed row + 16B pad
#define OFF_A 0
#define SZ_A  (64*ROWB)             // 17408
#define OFF_B (SZ_A)                // 17408
#define SZ_B  (64*ROWB)             // 17408
#define OFF_P (OFF_B + 2*SZ_B)      // 52224
#define SZ_P  1280                  // [0,1024) float4 xj ; [1024,1280) -cn2
#define OFF_M (OFF_P + 4*SZ_P)      // 57344 ; 64 rows x 5 floats
#define OFF_R (OFF_M + 64*5*4)      // 58624
#define SMEM_TOTAL (OFF_R + 64)     // 58688

// scratch (no allocation allowed)
__device__ __align__(16) uint32_t g_pk1[BATCH*NPTS*64]; // [hi64|lo64] bf16, f1*2log2e
__device__ __align__(16) uint32_t g_pk2[BATCH*NPTS*64]; // [hi64|lo64] bf16, f2 raw
__device__ __align__(16) float4   g_pi[BATCH*NPTS];     // xi*SC
__device__ __align__(16) float4   g_pj[BATCH*NPTS];     // xj*SC, w = -|xj|^2
__device__ __align__(16) float    g_cn2[BATCH*NPTS];    // NEGATED log2e*|f2|^2
__device__ float g_partial[BATCH*NIT];

__device__ __forceinline__ float ex2(float x){
    float y; asm("ex2.approx.ftz.f32 %0, %1;" : "=f"(y) : "f"(x)); return y;
}
__device__ __forceinline__ void cpa16(uint32_t dst, const void* src){
    asm volatile("cp.async.cg.shared.global [%0], [%1], 16;\n" :: "r"(dst), "l"(src));
}
__device__ __forceinline__ void ldmx4(uint32_t& r0,uint32_t& r1,uint32_t& r2,uint32_t& r3, uint32_t a){
    asm volatile("ldmatrix.sync.aligned.m8n8.x4.shared.b16 {%0,%1,%2,%3}, [%4];\n"
                 : "=r"(r0),"=r"(r1),"=r"(r2),"=r"(r3) : "r"(a));
}
__device__ __forceinline__ void mma16816(float* c, const uint32_t* a, uint32_t b0, uint32_t b1){
    asm volatile("mma.sync.aligned.m16n8k16.row.col.f32.bf16.bf16.f32 "
                 "{%0,%1,%2,%3}, {%4,%5,%6,%7}, {%8,%9}, {%0,%1,%2,%3};\n"
                 : "+f"(c[0]),"+f"(c[1]),"+f"(c[2]),"+f"(c[3])
                 : "r"(a[0]),"r"(a[1]),"r"(a[2]),"r"(a[3]), "r"(b0),"r"(b1));
}
// ---- packed f32x2 helpers (Blackwell FFMA2 path) ----
__device__ __forceinline__ uint64_t pk2(float lo, float hi){
    uint64_t r; asm("mov.b64 %0, {%1, %2};" : "=l"(r) : "f"(lo), "f"(hi)); return r;
}
__device__ __forceinline__ void upk2(uint64_t v, float& lo, float& hi){
    asm("mov.b64 {%0, %1}, %2;" : "=f"(lo), "=f"(hi) : "l"(v));
}
__device__ __forceinline__ uint64_t fma2(uint64_t a, uint64_t b, uint64_t c){
    uint64_t r; asm("fma.rn.f32x2 %0, %1, %2, %3;" : "=l"(r) : "l"(a), "l"(b), "l"(c)); return r;
}
__device__ __forceinline__ uint64_t add2(uint64_t a, uint64_t b){
    uint64_t r; asm("add.rn.f32x2 %0, %1, %2;" : "=l"(r) : "l"(a), "l"(b)); return r;
}

// ---------------------------------------------------------------------------
__global__ void prep_kernel(const float* __restrict__ pts,
                            const float* __restrict__ f1,
                            const float* __restrict__ f2)
{
    int gw   = (blockIdx.x*blockDim.x + threadIdx.x) >> 5;
    int lane = threadIdx.x & 31;
    if (gw >= BATCH*NPTS) return;
    const float* r1 = f1 + (size_t)gw*DIM;
    const float* r2 = f2 + (size_t)gw*DIM;
    float a0 = r1[lane], a1 = r1[lane+32];
    float b0 = r2[lane], b1 = r2[lane+32];
    float n2 = b0*b0 + b1*b1;
    #pragma unroll
    for (int o=16;o>=1;o>>=1) n2 += __shfl_xor_sync(~0u,n2,o);

    float s0 = a0*TWOL, s1 = a1*TWOL;
    __nv_bfloat16 h0=__float2bfloat16(s0), h1=__float2bfloat16(s1);
    __nv_bfloat16 l0=__float2bfloat16(s0-__bfloat162float(h0));
    __nv_bfloat16 l1=__float2bfloat16(s1-__bfloat162float(h1));
    __nv_bfloat16* o1 = (__nv_bfloat16*)(g_pk1 + (size_t)gw*64);
    o1[lane]=h0; o1[32+lane]=h1; o1[64+lane]=l0; o1[96+lane]=l1;

    __nv_bfloat16 H0=__float2bfloat16(b0), H1=__float2bfloat16(b1);
    __nv_bfloat16 L0=__float2bfloat16(b0-__bfloat162float(H0));
    __nv_bfloat16 L1=__float2bfloat16(b1-__bfloat162float(H1));
    __nv_bfloat16* o2 = (__nv_bfloat16*)(g_pk2 + (size_t)gw*64);
    o2[lane]=H0; o2[32+lane]=H1; o2[64+lane]=L0; o2[96+lane]=L1;

    if (lane==0){
        float px = pts[(size_t)gw*3+0]*SC_F;
        float py = pts[(size_t)gw*3+1]*SC_F;
        float pz = pts[(size_t)gw*3+2]*SC_F;
        g_pi[gw]  = make_float4(px,py,pz,0.0f);
        g_pj[gw]  = make_float4(px,py,pz, -fmaf(px,px, fmaf(py,py, pz*pz)));
        g_cn2[gw] = -(n2*LOG2E);          // NEGATED for packed add in epilogue
    }
}

// ---------------------------------------------------------------------------
__device__ __forceinline__ void load_B_tile(uint32_t sb, int tid, int b, int jt){
    const char* gB = (const char*)(g_pk2 + (size_t)(b*NPTS + jt*BN)*64);
    const uint32_t dst = sb + OFF_B + (jt&1)*SZ_B;
    #pragma unroll
    for(int q=0;q<4;q++){
        int idx=q*256+tid, r=idx>>4, c=idx&15;
        cpa16(dst + r*ROWB + c*16, gB + r*256 + c*16);
    }
    const uint32_t pdst = sb + OFF_P + (jt&3)*SZ_P;
    const int j0 = jt*BN;
    if (tid<64) cpa16(pdst + tid*16, (const char*)(g_pj + b*NPTS + j0 + tid));
    else if (tid<80) cpa16(pdst + 1024 + (tid-64)*16,
                           (const char*)(g_cn2 + b*NPTS + j0 + (tid-64)*4));
}

// ---------------------------------------------------------------------------
// 256 thr = 8 warps: wm=w&3 (row band of 16), wn=w>>2 (col band of 32).
// Warp tile 16 rows x 32 cols; A fragments in registers. Fixed-scale
// accumulation; epilogue packed f32x2 over the (h=0,h=1) row pair.
// ---------------------------------------------------------------------------
__global__ __launch_bounds__(256,2)
void loss_kernel(const float* __restrict__ wts)
{
    extern __shared__ __align__(16) char smem[];
    const uint32_t sb = (uint32_t)__cvta_generic_to_shared(smem);
    const int b  = blockIdx.y;
    const int i0 = blockIdx.x*BM;
    const int tid = threadIdx.x;
    const int w = tid>>5, lane = tid&31;
    const int wm = w&3, wn = w>>2;
    const int g = lane>>2, tig = lane&3;

    // prologue: A + B0 + P0 (group0), B1 + P1 (group1)
    {
        const char* gA = (const char*)(g_pk1 + (size_t)(b*NPTS+i0)*64);
        #pragma unroll
        for(int q=0;q<4;q++){
            int idx=q*256+tid, r=idx>>4, c=idx&15;
            cpa16(sb + OFF_A + r*ROWB + c*16, gA + r*256 + c*16);
        }
        load_B_tile(sb, tid, b, 0);
        asm volatile("cp.async.commit_group;\n");
        load_B_tile(sb, tid, b, 1);
        asm volatile("cp.async.commit_group;\n");
    }

    const uint32_t aAddr = sb + OFF_A + (wm*16 + (lane&15))*ROWB + (lane>>4)*16;
    const int bn_row = (lane&7) + (((lane>>4)&1)<<3);
    const uint32_t bk16 = ((lane>>3)&1)*16;

    // per-thread rows: r0 = wm*16+g, r1 = r0+8 ; packed constants (h0,h1)
    uint64_t x2xp, x2yp, x2zp, nnip;
    {
        int rl0 = wm*16 + g, rl1 = rl0 + 8;
        float4 v0 = g_pi[b*NPTS + i0 + rl0];
        float4 v1 = g_pi[b*NPTS + i0 + rl1];
        x2xp = pk2(v0.x+v0.x, v1.x+v1.x);
        x2yp = pk2(v0.y+v0.y, v1.y+v1.y);
        x2zp = pk2(v0.z+v0.z, v1.z+v1.z);
        nnip = pk2(-fmaf(v0.x,v0.x, fmaf(v0.y,v0.y, v0.z*v0.z)),
                   -fmaf(v1.x,v1.x, fmaf(v1.y,v1.y, v1.z*v1.z)));
    }
    uint64_t Z1p = pk2(0.f,0.f), Z2p = Z1p, Avp = Z1p, Bvp = Z1p, Cvp = Z1p;

    asm volatile("cp.async.wait_group 1;\n" ::: "memory");
    __syncthreads();

    // hoist A fragments (hi and lo): 8 ldmatrix.x4 = 32 regs
    uint32_t ah[4][4], al[4][4];
    #pragma unroll
    for(int c=0;c<4;c++){
        ldmx4(ah[c][0],ah[c][1],ah[c][2],ah[c][3], aAddr + c*32);
        ldmx4(al[c][0],al[c][1],al[c][2],al[c][3], aAddr + 128 + c*32);
    }

    for(int jt=0; jt<NJT; jt++){
        const int buf = jt&1;
        // ---- MMA: 4 k16-chunks x {HH,HL,LH}; B-only ldmatrix ----
        float acc[4][4];
        #pragma unroll
        for(int nb=0;nb<4;nb++)
            #pragma unroll
            for(int q=0;q<4;q++) acc[nb][q]=0.f;
        #pragma unroll
        for(int c=0;c<4;c++){
            #pragma unroll
            for(int n2=0;n2<2;n2++){
                uint32_t ba = sb + OFF_B + buf*SZ_B
                            + (wn*32 + n2*16 + bn_row)*ROWB + bk16;
                uint32_t bh[4], bl[4];
                ldmx4(bh[0],bh[1],bh[2],bh[3], ba + c*32);
                ldmx4(bl[0],bl[1],bl[2],bl[3], ba + 128 + c*32);
                mma16816(acc[n2*2+0], ah[c], bh[0], bh[1]);
                mma16816(acc[n2*2+1], ah[c], bh[2], bh[3]);
                mma16816(acc[n2*2+0], ah[c], bl[0], bl[1]);
                mma16816(acc[n2*2+1], ah[c], bl[2], bl[3]);
                mma16816(acc[n2*2+0], al[c], bh[0], bh[1]);
                mma16816(acc[n2*2+1], al[c], bh[2], bh[3]);
            }
        }

        // sync off the B buffer we just read, then prefetch jt+2 into it
        if (jt+1 < NJT){
            asm volatile("cp.async.wait_group 0;\n" ::: "memory");
        }
        __syncthreads();
        if (jt+2 < NJT){
            load_B_tile(sb, tid, b, jt+2);
            asm volatile("cp.async.commit_group;\n");
        }

        // ---- epilogue (fixed scale, f32x2 packed over the row pair) ----
        {
            const float4* pP = (const float4*)(smem + OFF_P + (jt&3)*SZ_P);
            const float*  pC = (const float*) (smem + OFF_P + (jt&3)*SZ_P + 1024);
            #pragma unroll
            for(int nb=0;nb<4;nb++){
                #pragma unroll
                for(int q=0;q<2;q++){
                    int c = wn*32 + nb*8 + tig*2 + q;
                    float4 v = pP[c];
                    float cn = pC[c];                       // already negated
                    // tt = 2xi.xj - |xi|^2 - |xj|^2 (both rows at once)
                    uint64_t ttp = fma2(x2xp, pk2(v.x,v.x),
                                   fma2(x2yp, pk2(v.y,v.y),
                                   fma2(x2zp, pk2(v.z,v.z),
                                   add2(pk2(v.w,v.w), nnip))));
                    uint64_t s2p = add2(pk2(acc[nb][q], acc[nb][2+q]),
                                        pk2(cn, cn));
                    float t0,t1, sa,sb2;
                    upk2(ttp, t0, t1);
                    upk2(s2p, sa, sb2);
                    float e1a = ex2(t0), e1b = ex2(t1);
                    float e2a = ex2(sa), e2b = ex2(sb2);
                    uint64_t e1p = pk2(e1a, e1b);
                    uint64_t e2p = pk2(e2a, e2b);
                    Z1p = add2(Z1p, e1p);
                    Avp = fma2(e1p, e1p, Avp);
                    Z2p = add2(Z2p, e2p);
                    Bvp = fma2(e2p, e2p, Bvp);
                    Cvp = fma2(e1p, e2p, Cvp);
                }
            }
        }
    }

    // unpack accumulators
    float Z1[2],Z2[2],Av[2],Bv[2],Cv[2];
    upk2(Z1p, Z1[0], Z1[1]);
    upk2(Z2p, Z2[0], Z2[1]);
    upk2(Avp, Av[0], Av[1]);
    upk2(Bvp, Bv[0], Bv[1]);
    upk2(Cvp, Cv[0], Cv[1]);

    // ---- merge 4 tig-lanes per row (plain sums) ----
    #pragma unroll
    for(int h=0;h<2;h++){
        #pragma unroll
        for(int off=1; off<=2; off<<=1){
            Z1[h] += __shfl_xor_sync(~0u, Z1[h], off);
            Z2[h] += __shfl_xor_sync(~0u, Z2[h], off);
            Av[h] += __shfl_xor_sync(~0u, Av[h], off);
            Bv[h] += __shfl_xor_sync(~0u, Bv[h], off);
            Cv[h] += __shfl_xor_sync(~0u, Cv[h], off);
        }
    }
    // ---- merge the two wn col-bands via smem ----
    float* sM = (float*)(smem + OFF_M);
    float* sR = (float*)(smem + OFF_R);
    if (wn==1 && tig==0){
        #pragma unroll
        for(int h=0;h<2;h++){
            int rl = wm*16 + g + h*8;
            float* p = sM + rl*5;
            p[0]=Z1[h]; p[1]=Z2[h]; p[2]=Av[h]; p[3]=Bv[h]; p[4]=Cv[h];
        }
    }
    __syncthreads();
    float wacc = 0.0f;
    if (wn==0 && tig==0){
        #pragma unroll
        for(int h=0;h<2;h++){
            int rl = wm*16 + g + h*8;
            const float* p = sM + rl*5;
            float Z1m = Z1[h] + p[0];
            float Z2m = Z2[h] + p[1];
            float Am  = Av[h] + p[2];
            float Bm  = Bv[h] + p[3];
            float Cm  = Cv[h] + p[4];
            float i1 = 1.0f/Z1m, i2 = 1.0f/Z2m;
            float loss = Am*i1*i1 - 2.0f*((Cm*i2)*i1) + (Bm*i2)*i2;
            wacc += wts[b*NPTS + i0 + rl] * loss;
        }
    }
    #pragma unroll
    for(int off=16; off>=1; off>>=1) wacc += __shfl_xor_sync(~0u, wacc, off);
    if (wn==0 && lane==0) sR[wm] = wacc;
    __syncthreads();
    if (tid==0)
        g_partial[b*NIT + blockIdx.x] = (sR[0]+sR[1]) + (sR[2]+sR[3]);
}

// ---------------------------------------------------------------------------
__global__ void reduce_kernel(float* __restrict__ out)
{
    int b    = threadIdx.x >> 5;
    int lane = threadIdx.x & 31;
    float s = g_partial[b*NIT + lane] + g_partial[b*NIT + 32 + lane];
    #pragma unroll
    for(int off=16; off>=1; off>>=1) s += __shfl_xor_sync(~0u, s, off);
    if (lane==0) out[b] = s;
}

// ---------------------------------------------------------------------------
extern "C" void kernel_launch(void* const* d_in, const int* in_sizes, int n_in,
                              void* d_out, int out_size)
{
    const float* pts = (const float*)d_in[0];
    const float* wts = (const float*)d_in[1];
    const float* f1  = (const float*)d_in[2];
    const float* f2  = (const float*)d_in[3];
    float* out = (float*)d_out;

    cudaFuncSetAttribute(loss_kernel, cudaFuncAttributeMaxDynamicSharedMemorySize, SMEM_TOTAL);
    prep_kernel<<<(BATCH*NPTS)/8, 256>>>(pts, f1, f2);
    dim3 grid(NIT, BATCH);
    loss_kernel<<<grid, 256, SMEM_TOTAL>>>(wts);
    reduce_kernel<<<1, 128>>>(out);
}